// round 9
// baseline (speedup 1.0000x reference)
#include <cuda_runtime.h>
#include <cuda_fp16.h>
#include <cuda_fp8.h>
#include <cstdint>
#include <math.h>

// ============================================================================
// Aligner: out = softmax((ix@W^T+b) @ (io@W^T+b)^T) @ io
// B=8, L=2048, D=1024, fp32 in/out.
// Round 9: fp8(e4m3) cross-term MMA fused into the scores GEMM.
//   M = W^T W (3-pass fp16);  t = ix@M (3-pass fp16);
//   S = t@io^T: fp16 hi*hi (operands pre-scaled 2^5/2^6) + ONE e4m3 K-
//      interleaved pass for (hi*lo + lo*hi), shared f32 acc scaled 2^11;
//   softmax(+r);  out = P@io (1-pass fp16).
// ============================================================================

#define BATCH 8
#define LSEQ  2048
#define DIM   1024
#define MELEMS ((size_t)BATCH * LSEQ * DIM)
#define SELEMS ((size_t)BATCH * LSEQ * LSEQ)

// ---- scratch (__device__ globals per allocation rules) ----
__device__ __half   g_ix_hi[MELEMS],  g_ix_lo[MELEMS];
__device__ __half   g_io_hs[MELEMS];            // io_hi * 64 (fp16)
__device__ uint8_t  g_io2[2 * MELEMS];          // {iol*4096, ioh*0.5} e4m3 pairs
__device__ __half   g_ioT_hi[MELEMS];
__device__ __half   g_t_hs[MELEMS];             // t_hi * 32 (fp16)
__device__ uint8_t  g_t2[2 * MELEMS];           // {th*0.5, tl*4096} e4m3 pairs
__device__ __half   g_wt_hi[DIM * DIM], g_wt_lo[DIM * DIM];
__device__ __half   g_m_hi[DIM * DIM],  g_m_lo[DIM * DIM];
__device__ float    g_s[SELEMS];
__device__ __half   g_p_hi[SELEMS];
__device__ float    g_p_vec[DIM];
__device__ float    g_r[(size_t)BATCH * LSEQ];

// ============================================================================
// PTX helpers (portable only)
// ============================================================================
__device__ __forceinline__ uint32_t smem_u32(const void* p) {
    uint32_t a;
    asm("{ .reg .u64 t; cvta.to.shared.u64 t, %1; cvt.u32.u64 %0, t; }"
        : "=r"(a) : "l"(p));
    return a;
}

#define CP_COMMIT() asm volatile("cp.async.commit_group;" ::: "memory")
#define CP_WAIT(N)  asm volatile("cp.async.wait_group %0;" :: "n"(N) : "memory")

__device__ __forceinline__ void cp16(uint32_t dst, const void* src) {
    asm volatile("cp.async.cg.shared.global [%0], [%1], 16;" :: "r"(dst), "l"(src));
}

__device__ __forceinline__ void ldsm4(uint32_t* r, uint32_t addr) {
    asm volatile("ldmatrix.sync.aligned.m8n8.x4.shared.b16 {%0,%1,%2,%3}, [%4];"
                 : "=r"(r[0]), "=r"(r[1]), "=r"(r[2]), "=r"(r[3]) : "r"(addr));
}

__device__ __forceinline__ void mma16816(float* d, const uint32_t* a,
                                         const uint32_t* b) {
    asm volatile(
        "mma.sync.aligned.m16n8k16.row.col.f32.f16.f16.f32 "
        "{%0,%1,%2,%3}, {%4,%5,%6,%7}, {%8,%9}, {%0,%1,%2,%3};"
        : "+f"(d[0]), "+f"(d[1]), "+f"(d[2]), "+f"(d[3])
        : "r"(a[0]), "r"(a[1]), "r"(a[2]), "r"(a[3]), "r"(b[0]), "r"(b[1]));
}

// fp8 e4m3 MMA: m16n8k32, f32 accumulate.
__device__ __forceinline__ void mma16832f8(float* d, const uint32_t* a,
                                           const uint32_t* b) {
    asm volatile(
        "mma.sync.aligned.m16n8k32.row.col.f32.e4m3.e4m3.f32 "
        "{%0,%1,%2,%3}, {%4,%5,%6,%7}, {%8,%9}, {%0,%1,%2,%3};"
        : "+f"(d[0]), "+f"(d[1]), "+f"(d[2]), "+f"(d[3])
        : "r"(a[0]), "r"(a[1]), "r"(a[2]), "r"(a[3]), "r"(b[0]), "r"(b[1]));
}

// tile layout: [rows][64 bytes], 16B chunks swizzled: chunk ^ ((row>>1)&3)
__device__ __forceinline__ uint32_t tile_addr(uint32_t base, int row, int chunk) {
    return base + row * 64 + ((chunk ^ ((row >> 1) & 3)) << 4);
}

__device__ __forceinline__ uint8_t to_e4m3(float v) {
    return (uint8_t)__nv_cvt_float_to_fp8(v, __NV_SATFINITE, __NV_E4M3);
}

// ============================================================================
// Helper kernels
// ============================================================================
__device__ __forceinline__ void split1(float v, __half& h, __half& l) {
    h = __float2half(v);
    l = __float2half(v - __half2float(h));
}

__global__ void split_f32(const float* __restrict__ s,
                          __half* __restrict__ hi,
                          __half* __restrict__ lo, size_t n) {
    size_t i = ((size_t)blockIdx.x * blockDim.x + threadIdx.x) * 4;
    if (i >= n) return;
    float4 v = *(const float4*)(s + i);
    __half h0, h1, h2, h3, l0, l1, l2, l3;
    split1(v.x, h0, l0); split1(v.y, h1, l1);
    split1(v.z, h2, l2); split1(v.w, h3, l3);
    *(__half2*)(hi + i)     = __halves2half2(h0, h1);
    *(__half2*)(hi + i + 2) = __halves2half2(h2, h3);
    *(__half2*)(lo + i)     = __halves2half2(l0, l1);
    *(__half2*)(lo + i + 2) = __halves2half2(l2, l3);
}

// io -> io_hs (fp16, hi*64) + io2 (e4m3 pairs {lo*4096, hi*0.5})
__global__ void split_io_fp8(const float* __restrict__ s,
                             __half* __restrict__ hs,
                             uint8_t* __restrict__ q, size_t n) {
    size_t i = ((size_t)blockIdx.x * blockDim.x + threadIdx.x) * 4;
    if (i >= n) return;
    float4 v = *(const float4*)(s + i);
    float vv[4] = {v.x, v.y, v.z, v.w};
    __half hsv[4];
    uint8_t qb[8];
    #pragma unroll
    for (int j = 0; j < 4; ++j) {
        __half h = __float2half(vv[j]);
        float hf = __half2float(h);
        float l  = vv[j] - hf;
        hsv[j] = __float2half(hf * 64.f);      // exact pow2 scale
        qb[2*j]   = to_e4m3(l * 4096.f);
        qb[2*j+1] = to_e4m3(hf * 0.5f);
    }
    *(__half2*)(hs + i)     = __halves2half2(hsv[0], hsv[1]);
    *(__half2*)(hs + i + 2) = __halves2half2(hsv[2], hsv[3]);
    *(uint2*)(q + 2 * i) = *(const uint2*)qb;
}

// per-batch transpose [rows, cols] -> [cols, rows]; lo output optional
__global__ void transpose_split(const float* __restrict__ src,
                                __half* __restrict__ hiT,
                                __half* __restrict__ loT,
                                int rows, int cols) {
    __shared__ float t[32][33];
    int b = blockIdx.z;
    int r0 = blockIdx.x * 32, c0 = blockIdx.y * 32;
    const float* s = src + (size_t)b * rows * cols;
    #pragma unroll
    for (int i = 0; i < 32; i += 8)
        t[threadIdx.y + i][threadIdx.x] =
            s[(size_t)(r0 + threadIdx.y + i) * cols + c0 + threadIdx.x];
    __syncthreads();
    size_t ob = (size_t)b * rows * cols;
    #pragma unroll
    for (int i = 0; i < 32; i += 8) {
        float v = t[threadIdx.x][threadIdx.y + i];
        __half h, l;
        split1(v, h, l);
        size_t o = ob + (size_t)(c0 + threadIdx.y + i) * rows + r0 + threadIdx.x;
        hiT[o] = h;
        if (loT) loT[o] = l;
    }
}

// p[i] = sum_k b[k] * W[k,i]
__global__ void compute_p(const float* __restrict__ W,
                          const float* __restrict__ b,
                          float* __restrict__ p) {
    int i = blockIdx.x * 128 + threadIdx.x;
    float acc = 0.f;
    for (int k = 0; k < DIM; ++k)
        acc += b[k] * W[(size_t)k * DIM + i];
    p[i] = acc;
}

// r[row] = io[row,:]·p   (one warp per row)
__global__ void compute_r(const float* __restrict__ io,
                          const float* __restrict__ p,
                          float* __restrict__ r) {
    int row  = blockIdx.x * 8 + (threadIdx.x >> 5);
    int lane = threadIdx.x & 31;
    const float* src = io + (size_t)row * DIM;
    float acc = 0.f;
    for (int d = lane * 4; d < DIM; d += 128) {
        float4 v  = *(const float4*)(src + d);
        float4 pv = *(const float4*)(p + d);
        acc += v.x * pv.x + v.y * pv.y + v.z * pv.z + v.w * pv.w;
    }
    #pragma unroll
    for (int o = 16; o; o >>= 1)
        acc += __shfl_xor_sync(0xFFFFFFFFu, acc, o);
    if (lane == 0) r[row] = acc;
}

// row softmax of (S[row,:] + r[b,:]); writes fp16 hi probabilities
__global__ void softmax_h(float* __restrict__ S,
                          const float* __restrict__ r,
                          __half* __restrict__ phi, int cols) {
    float* row = S + (size_t)blockIdx.x * cols;
    const float* rr = r + (size_t)(blockIdx.x / LSEQ) * LSEQ;
    __half* hr = phi + (size_t)blockIdx.x * cols;
    const int tid = threadIdx.x;

    float lmax = -3.0e38f;
    for (int i = tid * 4; i < cols; i += 1024) {
        float4 v = *(const float4*)(row + i);
        float4 a = *(const float4*)(rr + i);
        v.x += a.x; v.y += a.y; v.z += a.z; v.w += a.w;
        lmax = fmaxf(lmax, fmaxf(fmaxf(v.x, v.y), fmaxf(v.z, v.w)));
    }
    #pragma unroll
    for (int o = 16; o; o >>= 1)
        lmax = fmaxf(lmax, __shfl_xor_sync(0xFFFFFFFFu, lmax, o));
    __shared__ float sm[8], ss[8];
    if ((tid & 31) == 0) sm[tid >> 5] = lmax;
    __syncthreads();
    float rmax = fmaxf(fmaxf(fmaxf(sm[0], sm[1]), fmaxf(sm[2], sm[3])),
                       fmaxf(fmaxf(sm[4], sm[5]), fmaxf(sm[6], sm[7])));

    float lsum = 0.f;
    for (int i = tid * 4; i < cols; i += 1024) {
        float4 v = *(const float4*)(row + i);
        float4 a = *(const float4*)(rr + i);
        v.x = expf(v.x + a.x - rmax); v.y = expf(v.y + a.y - rmax);
        v.z = expf(v.z + a.z - rmax); v.w = expf(v.w + a.w - rmax);
        *(float4*)(row + i) = v;
        lsum += v.x + v.y + v.z + v.w;
    }
    #pragma unroll
    for (int o = 16; o; o >>= 1)
        lsum += __shfl_xor_sync(0xFFFFFFFFu, lsum, o);
    if ((tid & 31) == 0) ss[tid >> 5] = lsum;
    __syncthreads();
    float inv = 1.f / (ss[0]+ss[1]+ss[2]+ss[3]+ss[4]+ss[5]+ss[6]+ss[7]);

    for (int i = tid * 4; i < cols; i += 1024) {
        float4 v = *(const float4*)(row + i);
        __half h0 = __float2half(v.x * inv);
        __half h1 = __float2half(v.y * inv);
        __half h2 = __float2half(v.z * inv);
        __half h3 = __float2half(v.w * inv);
        *(__half2*)(hr + i)     = __halves2half2(h0, h1);
        *(__half2*)(hr + i + 2) = __halves2half2(h2, h3);
    }
}

// ============================================================================
// HMMA GEMM, CTA 128x128, warp tile 64x32, K-chunk 32, 3 stages, 2 CTAs/SM.
// MODE 3: 3-pass fp16 split (tiles Ah, Al, Bh, Bl)
// MODE 1: 1-pass fp16        (tiles Ah, Bh)
// MODE 8: fp16 hi pass + e4m3 interleaved cross pass (tiles Ahs, A2, Bhs, B2)
//         (fp8 tiles passed as __half* — pair-of-e4m3 per original k)
// Epilogue by pointers: Cf -> f32*out_scale; C2 -> fp8-pack (Chi=hs,C2=pairs);
//                       else split to Chi/Clo.
// ============================================================================
#define BKC 32
#define TILE_B 8192

template<int MODE>
__global__ __launch_bounds__(256, 2)
void gemm_split(const __half* __restrict__ Ahi, const __half* __restrict__ Alo,
                const __half* __restrict__ Bhi, const __half* __restrict__ Blo,
                float* __restrict__ Cf,
                __half* __restrict__ Chi, __half* __restrict__ Clo,
                uint8_t* __restrict__ C2, float out_scale,
                int K, int N,
                long long sA, long long sB, long long sC)
{
    constexpr int NT = (MODE == 1) ? 2 : 4;
    constexpr int STAGE_B = NT * TILE_B;
    constexpr int NSTAGE = 3;

    extern __shared__ __align__(128) char smem[];
    const uint32_t sb = smem_u32(smem);

    const int tid  = threadIdx.x;
    const int wid  = tid >> 5;
    const int lane = tid & 31;
    const int wm   = wid >> 2;
    const int wn   = wid & 3;

    const long long bz = blockIdx.z;
    const long long m0 = (long long)blockIdx.y * 128;
    const long long n0 = (long long)blockIdx.x * 128;

    const __half* srcs[4];
    srcs[0] = Ahi + bz * sA + m0 * K;
    if (MODE == 1) {
        srcs[1] = Bhi + bz * sB + n0 * K;
        srcs[2] = nullptr; srcs[3] = nullptr;
    } else {
        srcs[1] = Alo + bz * sA + m0 * K;     // MODE 8: A2 pairs viewed as half
        srcs[2] = Bhi + bz * sB + n0 * K;
        srcs[3] = Blo + bz * sB + n0 * K;     // MODE 8: B2 pairs viewed as half
    }

    auto load_chunk = [&](int stage, int k0) {
        const uint32_t base = sb + stage * STAGE_B;
        #pragma unroll
        for (int t = 0; t < NT; ++t) {
            #pragma unroll
            for (int j = 0; j < 2; ++j) {
                int idx = tid * 2 + j;
                int row = idx >> 2;
                int ch  = idx & 3;
                cp16(tile_addr(base + t * TILE_B, row, ch),
                     srcs[t] + (long long)row * K + k0 + ch * 8);
            }
        }
        CP_COMMIT();
    };

    float acc[4][4][4];
    #pragma unroll
    for (int i = 0; i < 4; ++i)
        #pragma unroll
        for (int j = 0; j < 4; ++j)
            #pragma unroll
            for (int e = 0; e < 4; ++e) acc[i][j][e] = 0.f;

    const int NC = K >> 5;
    load_chunk(0, 0);
    load_chunk(1, BKC);

    const int lrow = lane & 15;
    const int lch  = lane >> 4;

    for (int c = 0; c < NC; ++c) {
        if (c + 1 < NC) CP_WAIT(1); else CP_WAIT(0);
        __syncthreads();
        if (c + 2 < NC) load_chunk((c + 2) % NSTAGE, (c + 2) * BKC);

        const uint32_t st  = sb + (c % NSTAGE) * STAGE_B;
        const uint32_t sA0 = st;
        const uint32_t sA1 = st + TILE_B;                       // MODE 3/8
        const uint32_t sB0 = st + ((MODE == 1) ? 1 : 2) * TILE_B;
        const uint32_t sB1 = st + 3 * TILE_B;                   // MODE 3/8

        #pragma unroll
        for (int ks = 0; ks < 2; ++ks) {
            const int chunk = ks * 2 + lch;
            uint32_t a0[4][4], a1[4][4];
            uint32_t b0[4][2], b1[4][2];

            #pragma unroll
            for (int mi = 0; mi < 4; ++mi) {
                const int row = wm * 64 + mi * 16 + lrow;
                ldsm4(a0[mi], tile_addr(sA0, row, chunk));
                if (MODE != 1)
                    ldsm4(a1[mi], tile_addr(sA1, row, chunk));
            }
            #pragma unroll
            for (int bi = 0; bi < 2; ++bi) {
                const int row = wn * 32 + bi * 16 + lrow;
                uint32_t t4[4];
                ldsm4(t4, tile_addr(sB0, row, chunk));
                b0[bi*2][0]   = t4[0]; b0[bi*2][1]   = t4[2];
                b0[bi*2+1][0] = t4[1]; b0[bi*2+1][1] = t4[3];
                if (MODE != 1) {
                    ldsm4(t4, tile_addr(sB1, row, chunk));
                    b1[bi*2][0]   = t4[0]; b1[bi*2][1]   = t4[2];
                    b1[bi*2+1][0] = t4[1]; b1[bi*2+1][1] = t4[3];
                }
            }

            #pragma unroll
            for (int mi = 0; mi < 4; ++mi)
                #pragma unroll
                for (int ni = 0; ni < 4; ++ni) {
                    mma16816(acc[mi][ni], a0[mi], b0[ni]);
                    if (MODE == 3) {
                        mma16816(acc[mi][ni], a0[mi], b1[ni]);
                        mma16816(acc[mi][ni], a1[mi], b0[ni]);
                    } else if (MODE == 8) {
                        mma16832f8(acc[mi][ni], a1[mi], b1[ni]);
                    }
                }
        }
        __syncthreads();
    }

    // ---- epilogue ----
    const int r1 = lane >> 2;
    const int c0i = (lane & 3) * 2;
    #pragma unroll
    for (int mi = 0; mi < 4; ++mi) {
        #pragma unroll
        for (int ni = 0; ni < 4; ++ni) {
            const long long gm = m0 + wm * 64 + mi * 16 + r1;
            const long long gn = n0 + wn * 32 + ni * 8 + c0i;
            float v0 = acc[mi][ni][0], v1 = acc[mi][ni][1];
            float v2 = acc[mi][ni][2], v3 = acc[mi][ni][3];
            if (Cf) {
                float* d0 = Cf + bz * sC + gm * N + gn;
                float* d1 = Cf + bz * sC + (gm + 8) * N + gn;
                d0[0] = v0 * out_scale; d0[1] = v1 * out_scale;
                d1[0] = v2 * out_scale; d1[1] = v3 * out_scale;
            } else if (C2) {
                // fp8-pack mode: Chi = hs (hi*32), C2 = {h*0.5, l*4096} pairs
                #pragma unroll
                for (int half_i = 0; half_i < 2; ++half_i) {
                    float w0 = half_i ? v2 : v0;
                    float w1 = half_i ? v3 : v1;
                    long long row = gm + half_i * 8;
                    __half h0 = __float2half(w0);
                    __half h1 = __float2half(w1);
                    float hf0 = __half2float(h0), hf1 = __half2float(h1);
                    float l0 = w0 - hf0, l1 = w1 - hf1;
                    *(__half2*)(Chi + bz * sC + row * N + gn) =
                        __halves2half2(__float2half(hf0 * 32.f),
                                       __float2half(hf1 * 32.f));
                    uint8_t qb[4];
                    qb[0] = to_e4m3(hf0 * 0.5f);
                    qb[1] = to_e4m3(l0 * 4096.f);
                    qb[2] = to_e4m3(hf1 * 0.5f);
                    qb[3] = to_e4m3(l1 * 4096.f);
                    *(uint32_t*)(C2 + 2 * (bz * sC + row * N + gn)) =
                        *(const uint32_t*)qb;
                }
            } else {
                __half h0, h1, h2, h3, l0, l1, l2, l3;
                split1(v0, h0, l0); split1(v1, h1, l1);
                split1(v2, h2, l2); split1(v3, h3, l3);
                *(__half2*)(Chi + bz * sC + gm * N + gn)       = __halves2half2(h0, h1);
                *(__half2*)(Clo + bz * sC + gm * N + gn)       = __halves2half2(l0, l1);
                *(__half2*)(Chi + bz * sC + (gm + 8) * N + gn) = __halves2half2(h2, h3);
                *(__half2*)(Clo + bz * sC + (gm + 8) * N + gn) = __halves2half2(l2, l3);
            }
        }
    }
}

// ============================================================================
extern "C" void kernel_launch(void* const* d_in, const int* in_sizes, int n_in,
                              void* d_out, int out_size)
{
    const float* ix = (const float*)d_in[0];
    const float* io = (const float*)d_in[1];
    const float* W  = (const float*)d_in[2];
    const float* bb = (const float*)d_in[3];
    float* out = (float*)d_out;

    __half *ix_hi, *ix_lo, *io_hs, *ioT_hi, *t_hs, *wt_hi, *wt_lo, *m_hi, *m_lo, *p_hi;
    uint8_t *io2, *t2;
    float *s, *pv, *rv;
    cudaGetSymbolAddress((void**)&ix_hi, g_ix_hi);
    cudaGetSymbolAddress((void**)&ix_lo, g_ix_lo);
    cudaGetSymbolAddress((void**)&io_hs, g_io_hs);
    cudaGetSymbolAddress((void**)&io2,   g_io2);
    cudaGetSymbolAddress((void**)&ioT_hi, g_ioT_hi);
    cudaGetSymbolAddress((void**)&t_hs, g_t_hs);
    cudaGetSymbolAddress((void**)&t2,   g_t2);
    cudaGetSymbolAddress((void**)&wt_hi, g_wt_hi);
    cudaGetSymbolAddress((void**)&wt_lo, g_wt_lo);
    cudaGetSymbolAddress((void**)&m_hi, g_m_hi);
    cudaGetSymbolAddress((void**)&m_lo, g_m_lo);
    cudaGetSymbolAddress((void**)&p_hi, g_p_hi);
    cudaGetSymbolAddress((void**)&s, g_s);
    cudaGetSymbolAddress((void**)&pv, g_p_vec);
    cudaGetSymbolAddress((void**)&rv, g_r);

    static bool attr_set = false;
    const int smem4 = 3 * 4 * TILE_B;   // 96 KB (MODE 3, 8)
    const int smem1 = 3 * 2 * TILE_B;   // 48 KB (MODE 1)
    if (!attr_set) {
        cudaFuncSetAttribute(gemm_split<3>,
                             cudaFuncAttributeMaxDynamicSharedMemorySize, smem4);
        cudaFuncSetAttribute(gemm_split<8>,
                             cudaFuncAttributeMaxDynamicSharedMemorySize, smem4);
        cudaFuncSetAttribute(gemm_split<1>,
                             cudaFuncAttributeMaxDynamicSharedMemorySize, smem1);
        attr_set = true;
    }

    // 1) W^T split
    transpose_split<<<dim3(DIM / 32, DIM / 32, 1), dim3(32, 8)>>>(
        W, wt_hi, wt_lo, DIM, DIM);

    // 2) M = W^T W (symmetric), 3-pass -> fp16 split
    {
        dim3 g(DIM / 128, DIM / 128, 1);
        gemm_split<3><<<g, 256, smem4>>>(wt_hi, wt_lo, wt_hi, wt_lo,
                                         nullptr, m_hi, m_lo, nullptr, 1.f,
                                         DIM, DIM, 0, 0, 0);
    }

    // 3) ix split
    split_f32<<<(unsigned)(MELEMS / 4 / 256), 256>>>(ix, ix_hi, ix_lo, MELEMS);

    // 4) t = ix @ M, 3-pass -> t_hs (fp16*32) + t2 (e4m3 pairs)
    {
        dim3 g(DIM / 128, (BATCH * LSEQ) / 128, 1);
        gemm_split<3><<<g, 256, smem4>>>(ix_hi, ix_lo, m_hi, m_lo,
                                         nullptr, t_hs, nullptr, t2, 1.f,
                                         DIM, DIM, 0, 0, 0);
    }

    // 5) io -> io_hs (fp16*64) + io2 (e4m3 pairs)
    split_io_fp8<<<(unsigned)(MELEMS / 4 / 256), 256>>>(io, io_hs, io2, MELEMS);

    // 6) scores: S[b] = t[b] @ io[b]^T, fp16-hi + fp8-cross, scale 2^-11
    //    (6th launch -> ncu profiled)
    {
        dim3 g(LSEQ / 128, LSEQ / 128, BATCH);
        gemm_split<8><<<g, 256, smem4>>>(t_hs, (const __half*)t2,
                                         io_hs, (const __half*)io2,
                                         s, nullptr, nullptr, nullptr,
                                         1.f / 2048.f,
                                         DIM, LSEQ,
                                         (long long)LSEQ * DIM,
                                         (long long)LSEQ * DIM,
                                         (long long)LSEQ * LSEQ);
    }

    // 7) io^T for out-gemm
    transpose_split<<<dim3(LSEQ / 32, DIM / 32, BATCH), dim3(32, 8)>>>(
        io, ioT_hi, (__half*)nullptr, LSEQ, DIM);

    // 8-9) bias-fold vectors
    compute_p<<<DIM / 128, 128>>>(W, bb, pv);
    compute_r<<<(BATCH * LSEQ) / 8, 256>>>(io, pv, rv);

    // 10) softmax(S + r) -> P fp16
    softmax_h<<<BATCH * LSEQ, 256>>>(s, rv, p_hi, LSEQ);

    // 11) out[b] = P[b] @ ioT[b]^T, 1-pass fp16 -> fp32 d_out
    {
        dim3 g(DIM / 128, LSEQ / 128, BATCH);
        gemm_split<1><<<g, 256, smem1>>>(p_hi, nullptr, ioT_hi, nullptr,
                                         out, nullptr, nullptr, nullptr, 1.f,
                                         LSEQ, DIM,
                                         (long long)LSEQ * LSEQ,
                                         (long long)DIM * LSEQ,
                                         (long long)LSEQ * DIM);
    }
}

// round 10
// speedup vs baseline: 1.0149x; 1.0149x over previous
#include <cuda_runtime.h>
#include <cuda_fp16.h>
#include <cstdint>
#include <math.h>

// ============================================================================
// Aligner: out = softmax((ix@W^T+b) @ (io@W^T+b)^T) @ io
// B=8, L=2048, D=1024, fp32 in/out.
// Round 10: R8 pipeline (fp16 split; M=W^T W; t=ix@M; S=t@io^T; out=P@io
// 1-pass) with PASS-MAJOR MMA ordering: dependent MMAs on the same
// accumulator are now 16 independent MMAs apart (was back-to-back, which
// serialized on HMMA latency and capped tensor pipe at ~48%).
// ============================================================================

#define BATCH 8
#define LSEQ  2048
#define DIM   1024
#define MELEMS ((size_t)BATCH * LSEQ * DIM)
#define SELEMS ((size_t)BATCH * LSEQ * LSEQ)

// ---- scratch (__device__ globals per allocation rules) ----
__device__ __half g_ix_hi[MELEMS],  g_ix_lo[MELEMS];
__device__ __half g_io_hi[MELEMS],  g_io_lo[MELEMS];
__device__ __half g_ioT_hi[MELEMS];
__device__ __half g_t_hi[MELEMS],   g_t_lo[MELEMS];
__device__ __half g_wt_hi[DIM * DIM], g_wt_lo[DIM * DIM];
__device__ __half g_m_hi[DIM * DIM],  g_m_lo[DIM * DIM];
__device__ float  g_s[SELEMS];
__device__ __half g_p_hi[SELEMS];
__device__ float  g_p_vec[DIM];
__device__ float  g_r[(size_t)BATCH * LSEQ];

// ============================================================================
// PTX helpers (portable only)
// ============================================================================
__device__ __forceinline__ uint32_t smem_u32(const void* p) {
    uint32_t a;
    asm("{ .reg .u64 t; cvta.to.shared.u64 t, %1; cvt.u32.u64 %0, t; }"
        : "=r"(a) : "l"(p));
    return a;
}

#define CP_COMMIT() asm volatile("cp.async.commit_group;" ::: "memory")
#define CP_WAIT(N)  asm volatile("cp.async.wait_group %0;" :: "n"(N) : "memory")

__device__ __forceinline__ void cp16(uint32_t dst, const void* src) {
    asm volatile("cp.async.cg.shared.global [%0], [%1], 16;" :: "r"(dst), "l"(src));
}

__device__ __forceinline__ void ldsm4(uint32_t* r, uint32_t addr) {
    asm volatile("ldmatrix.sync.aligned.m8n8.x4.shared.b16 {%0,%1,%2,%3}, [%4];"
                 : "=r"(r[0]), "=r"(r[1]), "=r"(r[2]), "=r"(r[3]) : "r"(addr));
}

__device__ __forceinline__ void mma16816(float* d, const uint32_t* a,
                                         const uint32_t* b) {
    asm volatile(
        "mma.sync.aligned.m16n8k16.row.col.f32.f16.f16.f32 "
        "{%0,%1,%2,%3}, {%4,%5,%6,%7}, {%8,%9}, {%0,%1,%2,%3};"
        : "+f"(d[0]), "+f"(d[1]), "+f"(d[2]), "+f"(d[3])
        : "r"(a[0]), "r"(a[1]), "r"(a[2]), "r"(a[3]), "r"(b[0]), "r"(b[1]));
}

// tile layout: [rows][64 bytes], 16B chunks swizzled: chunk ^ ((row>>1)&3)
__device__ __forceinline__ uint32_t tile_addr(uint32_t base, int row, int chunk) {
    return base + row * 64 + ((chunk ^ ((row >> 1) & 3)) << 4);
}

// ============================================================================
// Helper kernels
// ============================================================================
__device__ __forceinline__ void split1(float v, __half& h, __half& l) {
    h = __float2half(v);
    l = __float2half(v - __half2float(h));
}

__global__ void split_f32(const float* __restrict__ s,
                          __half* __restrict__ hi,
                          __half* __restrict__ lo, size_t n) {
    size_t i = ((size_t)blockIdx.x * blockDim.x + threadIdx.x) * 4;
    if (i >= n) return;
    float4 v = *(const float4*)(s + i);
    __half h0, h1, h2, h3, l0, l1, l2, l3;
    split1(v.x, h0, l0); split1(v.y, h1, l1);
    split1(v.z, h2, l2); split1(v.w, h3, l3);
    *(__half2*)(hi + i)     = __halves2half2(h0, h1);
    *(__half2*)(hi + i + 2) = __halves2half2(h2, h3);
    *(__half2*)(lo + i)     = __halves2half2(l0, l1);
    *(__half2*)(lo + i + 2) = __halves2half2(l2, l3);
}

// per-batch transpose [rows, cols] -> [cols, rows]; lo output optional
__global__ void transpose_split(const float* __restrict__ src,
                                __half* __restrict__ hiT,
                                __half* __restrict__ loT,
                                int rows, int cols) {
    __shared__ float t[32][33];
    int b = blockIdx.z;
    int r0 = blockIdx.x * 32, c0 = blockIdx.y * 32;
    const float* s = src + (size_t)b * rows * cols;
    #pragma unroll
    for (int i = 0; i < 32; i += 8)
        t[threadIdx.y + i][threadIdx.x] =
            s[(size_t)(r0 + threadIdx.y + i) * cols + c0 + threadIdx.x];
    __syncthreads();
    size_t ob = (size_t)b * rows * cols;
    #pragma unroll
    for (int i = 0; i < 32; i += 8) {
        float v = t[threadIdx.x][threadIdx.y + i];
        __half h, l;
        split1(v, h, l);
        size_t o = ob + (size_t)(c0 + threadIdx.y + i) * rows + r0 + threadIdx.x;
        hiT[o] = h;
        if (loT) loT[o] = l;
    }
}

// p[i] = sum_k b[k] * W[k,i]
__global__ void compute_p(const float* __restrict__ W,
                          const float* __restrict__ b,
                          float* __restrict__ p) {
    int i = blockIdx.x * 128 + threadIdx.x;
    float acc = 0.f;
    for (int k = 0; k < DIM; ++k)
        acc += b[k] * W[(size_t)k * DIM + i];
    p[i] = acc;
}

// r[row] = io[row,:]·p   (one warp per row)
__global__ void compute_r(const float* __restrict__ io,
                          const float* __restrict__ p,
                          float* __restrict__ r) {
    int row  = blockIdx.x * 8 + (threadIdx.x >> 5);
    int lane = threadIdx.x & 31;
    const float* src = io + (size_t)row * DIM;
    float acc = 0.f;
    for (int d = lane * 4; d < DIM; d += 128) {
        float4 v  = *(const float4*)(src + d);
        float4 pv = *(const float4*)(p + d);
        acc += v.x * pv.x + v.y * pv.y + v.z * pv.z + v.w * pv.w;
    }
    #pragma unroll
    for (int o = 16; o; o >>= 1)
        acc += __shfl_xor_sync(0xFFFFFFFFu, acc, o);
    if (lane == 0) r[row] = acc;
}

// row softmax of (S[row,:] + r[b,:]); writes fp16 hi probabilities only
__global__ void softmax_h(float* __restrict__ S,
                          const float* __restrict__ r,
                          __half* __restrict__ phi, int cols) {
    float* row = S + (size_t)blockIdx.x * cols;
    const float* rr = r + (size_t)(blockIdx.x / LSEQ) * LSEQ;
    __half* hr = phi + (size_t)blockIdx.x * cols;
    const int tid = threadIdx.x;

    float lmax = -3.0e38f;
    for (int i = tid * 4; i < cols; i += 1024) {
        float4 v = *(const float4*)(row + i);
        float4 a = *(const float4*)(rr + i);
        v.x += a.x; v.y += a.y; v.z += a.z; v.w += a.w;
        lmax = fmaxf(lmax, fmaxf(fmaxf(v.x, v.y), fmaxf(v.z, v.w)));
    }
    #pragma unroll
    for (int o = 16; o; o >>= 1)
        lmax = fmaxf(lmax, __shfl_xor_sync(0xFFFFFFFFu, lmax, o));
    __shared__ float sm[8], ss[8];
    if ((tid & 31) == 0) sm[tid >> 5] = lmax;
    __syncthreads();
    float rmax = fmaxf(fmaxf(fmaxf(sm[0], sm[1]), fmaxf(sm[2], sm[3])),
                       fmaxf(fmaxf(sm[4], sm[5]), fmaxf(sm[6], sm[7])));

    float lsum = 0.f;
    for (int i = tid * 4; i < cols; i += 1024) {
        float4 v = *(const float4*)(row + i);
        float4 a = *(const float4*)(rr + i);
        v.x = expf(v.x + a.x - rmax); v.y = expf(v.y + a.y - rmax);
        v.z = expf(v.z + a.z - rmax); v.w = expf(v.w + a.w - rmax);
        *(float4*)(row + i) = v;
        lsum += v.x + v.y + v.z + v.w;
    }
    #pragma unroll
    for (int o = 16; o; o >>= 1)
        lsum += __shfl_xor_sync(0xFFFFFFFFu, lsum, o);
    if ((tid & 31) == 0) ss[tid >> 5] = lsum;
    __syncthreads();
    float inv = 1.f / (ss[0]+ss[1]+ss[2]+ss[3]+ss[4]+ss[5]+ss[6]+ss[7]);

    for (int i = tid * 4; i < cols; i += 1024) {
        float4 v = *(const float4*)(row + i);
        __half h0 = __float2half(v.x * inv);
        __half h1 = __float2half(v.y * inv);
        __half h2 = __float2half(v.z * inv);
        __half h3 = __float2half(v.w * inv);
        *(__half2*)(hr + i)     = __halves2half2(h0, h1);
        *(__half2*)(hr + i + 2) = __halves2half2(h2, h3);
    }
}

// ============================================================================
// Split-precision HMMA GEMM, CTA 128x128, warp tile 64x32, K-chunk 32.
// 3 smem stages (prefetch depth 2), 2 CTAs/SM.
// NPASS=3: C = Ah*Bh + Ah*Bl + Al*Bh  — MMAs issued PASS-MAJOR so that
//          writes to the same accumulator are 16 independent MMAs apart.
// NPASS=1: C = Ah*Bh.
// ============================================================================
#define BKC 32
#define TILE_B 8192

template<int NPASS>
__global__ __launch_bounds__(256, 2)
void gemm_split(const __half* __restrict__ Ahi, const __half* __restrict__ Alo,
                const __half* __restrict__ Bhi, const __half* __restrict__ Blo,
                float* __restrict__ Cf,
                __half* __restrict__ Chi, __half* __restrict__ Clo,
                int K, int N,
                long long sA, long long sB, long long sC)
{
    constexpr int NT = (NPASS == 3) ? 4 : 2;
    constexpr int STAGE_B = NT * TILE_B;
    constexpr int NSTAGE = 3;

    extern __shared__ __align__(128) char smem[];
    const uint32_t sb = smem_u32(smem);

    const int tid  = threadIdx.x;
    const int wid  = tid >> 5;
    const int lane = tid & 31;
    const int wm   = wid >> 2;
    const int wn   = wid & 3;

    const long long bz = blockIdx.z;
    const long long m0 = (long long)blockIdx.y * 128;
    const long long n0 = (long long)blockIdx.x * 128;

    const __half* srcs[4];
    srcs[0] = Ahi + bz * sA + m0 * K;
    if (NPASS == 3) {
        srcs[1] = Alo + bz * sA + m0 * K;
        srcs[2] = Bhi + bz * sB + n0 * K;
        srcs[3] = Blo + bz * sB + n0 * K;
    } else {
        srcs[1] = Bhi + bz * sB + n0 * K;
        srcs[2] = nullptr;
        srcs[3] = nullptr;
    }

    auto load_chunk = [&](int stage, int k0) {
        const uint32_t base = sb + stage * STAGE_B;
        #pragma unroll
        for (int t = 0; t < NT; ++t) {
            #pragma unroll
            for (int j = 0; j < 2; ++j) {
                int idx = tid * 2 + j;
                int row = idx >> 2;
                int ch  = idx & 3;
                cp16(tile_addr(base + t * TILE_B, row, ch),
                     srcs[t] + (long long)row * K + k0 + ch * 8);
            }
        }
        CP_COMMIT();
    };

    float acc[4][4][4];
    #pragma unroll
    for (int i = 0; i < 4; ++i)
        #pragma unroll
        for (int j = 0; j < 4; ++j)
            #pragma unroll
            for (int e = 0; e < 4; ++e) acc[i][j][e] = 0.f;

    const int NC = K >> 5;
    load_chunk(0, 0);
    load_chunk(1, BKC);

    const int lrow = lane & 15;
    const int lch  = lane >> 4;

    for (int c = 0; c < NC; ++c) {
        if (c + 1 < NC) CP_WAIT(1); else CP_WAIT(0);
        __syncthreads();
        if (c + 2 < NC) load_chunk((c + 2) % NSTAGE, (c + 2) * BKC);

        const uint32_t st  = sb + (c % NSTAGE) * STAGE_B;
        const uint32_t sAh = st;
        const uint32_t sAl = st + TILE_B;                      // NPASS==3 only
        const uint32_t sBh = st + ((NPASS == 3) ? 2 : 1) * TILE_B;
        const uint32_t sBl = st + 3 * TILE_B;                  // NPASS==3 only

        #pragma unroll
        for (int ks = 0; ks < 2; ++ks) {
            const int chunk = ks * 2 + lch;
            uint32_t ahi[4][4], alo[4][4];
            uint32_t bhi[4][2], blo[4][2];

            #pragma unroll
            for (int mi = 0; mi < 4; ++mi) {
                const int row = wm * 64 + mi * 16 + lrow;
                ldsm4(ahi[mi], tile_addr(sAh, row, chunk));
                if (NPASS == 3)
                    ldsm4(alo[mi], tile_addr(sAl, row, chunk));
            }
            #pragma unroll
            for (int bi = 0; bi < 2; ++bi) {
                const int row = wn * 32 + bi * 16 + lrow;
                uint32_t t4[4];
                ldsm4(t4, tile_addr(sBh, row, chunk));
                bhi[bi*2][0]   = t4[0]; bhi[bi*2][1]   = t4[2];
                bhi[bi*2+1][0] = t4[1]; bhi[bi*2+1][1] = t4[3];
                if (NPASS == 3) {
                    ldsm4(t4, tile_addr(sBl, row, chunk));
                    blo[bi*2][0]   = t4[0]; blo[bi*2][1]   = t4[2];
                    blo[bi*2+1][0] = t4[1]; blo[bi*2+1][1] = t4[3];
                }
            }

            // PASS-MAJOR: 16 independent MMAs between writes to the same acc.
            #pragma unroll
            for (int mi = 0; mi < 4; ++mi)
                #pragma unroll
                for (int ni = 0; ni < 4; ++ni)
                    mma16816(acc[mi][ni], ahi[mi], bhi[ni]);
            if (NPASS == 3) {
                #pragma unroll
                for (int mi = 0; mi < 4; ++mi)
                    #pragma unroll
                    for (int ni = 0; ni < 4; ++ni)
                        mma16816(acc[mi][ni], ahi[mi], blo[ni]);
                #pragma unroll
                for (int mi = 0; mi < 4; ++mi)
                    #pragma unroll
                    for (int ni = 0; ni < 4; ++ni)
                        mma16816(acc[mi][ni], alo[mi], bhi[ni]);
            }
        }
        __syncthreads();
    }

    // ---- epilogue ----
    const int r1 = lane >> 2;
    const int c0 = (lane & 3) * 2;
    #pragma unroll
    for (int mi = 0; mi < 4; ++mi) {
        #pragma unroll
        for (int ni = 0; ni < 4; ++ni) {
            const long long gm = m0 + wm * 64 + mi * 16 + r1;
            const long long gn = n0 + wn * 32 + ni * 8 + c0;
            float v0 = acc[mi][ni][0], v1 = acc[mi][ni][1];
            float v2 = acc[mi][ni][2], v3 = acc[mi][ni][3];
            if (Cf) {
                float* d0 = Cf + bz * sC + gm * N + gn;
                float* d1 = Cf + bz * sC + (gm + 8) * N + gn;
                d0[0] = v0; d0[1] = v1;
                d1[0] = v2; d1[1] = v3;
            } else {
                __half h0, h1, h2, h3, l0, l1, l2, l3;
                split1(v0, h0, l0); split1(v1, h1, l1);
                split1(v2, h2, l2); split1(v3, h3, l3);
                *(__half2*)(Chi + bz * sC + gm * N + gn)       = __halves2half2(h0, h1);
                *(__half2*)(Clo + bz * sC + gm * N + gn)       = __halves2half2(l0, l1);
                *(__half2*)(Chi + bz * sC + (gm + 8) * N + gn) = __halves2half2(h2, h3);
                *(__half2*)(Clo + bz * sC + (gm + 8) * N + gn) = __halves2half2(l2, l3);
            }
        }
    }
}

// ============================================================================
extern "C" void kernel_launch(void* const* d_in, const int* in_sizes, int n_in,
                              void* d_out, int out_size)
{
    const float* ix = (const float*)d_in[0];
    const float* io = (const float*)d_in[1];
    const float* W  = (const float*)d_in[2];
    const float* bb = (const float*)d_in[3];
    float* out = (float*)d_out;

    __half *ix_hi, *ix_lo, *io_hi, *io_lo, *ioT_hi;
    __half *t_hi, *t_lo, *wt_hi, *wt_lo, *m_hi, *m_lo, *p_hi;
    float *s, *pv, *rv;
    cudaGetSymbolAddress((void**)&ix_hi, g_ix_hi);
    cudaGetSymbolAddress((void**)&ix_lo, g_ix_lo);
    cudaGetSymbolAddress((void**)&io_hi, g_io_hi);
    cudaGetSymbolAddress((void**)&io_lo, g_io_lo);
    cudaGetSymbolAddress((void**)&ioT_hi, g_ioT_hi);
    cudaGetSymbolAddress((void**)&t_hi, g_t_hi);
    cudaGetSymbolAddress((void**)&t_lo, g_t_lo);
    cudaGetSymbolAddress((void**)&wt_hi, g_wt_hi);
    cudaGetSymbolAddress((void**)&wt_lo, g_wt_lo);
    cudaGetSymbolAddress((void**)&m_hi, g_m_hi);
    cudaGetSymbolAddress((void**)&m_lo, g_m_lo);
    cudaGetSymbolAddress((void**)&p_hi, g_p_hi);
    cudaGetSymbolAddress((void**)&s, g_s);
    cudaGetSymbolAddress((void**)&pv, g_p_vec);
    cudaGetSymbolAddress((void**)&rv, g_r);

    static bool attr_set = false;
    const int smem3 = 3 * 4 * TILE_B;   // 96 KB (NPASS=3)
    const int smem1 = 3 * 2 * TILE_B;   // 48 KB (NPASS=1)
    if (!attr_set) {
        cudaFuncSetAttribute(gemm_split<3>,
                             cudaFuncAttributeMaxDynamicSharedMemorySize, smem3);
        cudaFuncSetAttribute(gemm_split<1>,
                             cudaFuncAttributeMaxDynamicSharedMemorySize, smem1);
        attr_set = true;
    }

    // 1) W^T split
    transpose_split<<<dim3(DIM / 32, DIM / 32, 1), dim3(32, 8)>>>(
        W, wt_hi, wt_lo, DIM, DIM);

    // 2) M = W^T W (symmetric), 3-pass -> fp16 split
    {
        dim3 g(DIM / 128, DIM / 128, 1);
        gemm_split<3><<<g, 256, smem3>>>(wt_hi, wt_lo, wt_hi, wt_lo,
                                         nullptr, m_hi, m_lo,
                                         DIM, DIM, 0, 0, 0);
    }

    // 3) ix split
    split_f32<<<(unsigned)(MELEMS / 4 / 256), 256>>>(ix, ix_hi, ix_lo, MELEMS);

    // 4) t = ix @ M (symmetric), 3-pass -> fp16 split
    {
        dim3 g(DIM / 128, (BATCH * LSEQ) / 128, 1);
        gemm_split<3><<<g, 256, smem3>>>(ix_hi, ix_lo, m_hi, m_lo,
                                         nullptr, t_hi, t_lo,
                                         DIM, DIM, 0, 0, 0);
    }

    // 5) io split
    split_f32<<<(unsigned)(MELEMS / 4 / 256), 256>>>(io, io_hi, io_lo, MELEMS);

    // 6) scores: S[b] = t[b] @ io[b]^T, 3-pass -> fp32
    {
        dim3 g(LSEQ / 128, LSEQ / 128, BATCH);
        gemm_split<3><<<g, 256, smem3>>>(t_hi, t_lo, io_hi, io_lo,
                                         s, nullptr, nullptr,
                                         DIM, LSEQ,
                                         (long long)LSEQ * DIM,
                                         (long long)LSEQ * DIM,
                                         (long long)LSEQ * LSEQ);
    }

    // 7) io^T for out-gemm
    transpose_split<<<dim3(LSEQ / 32, DIM / 32, BATCH), dim3(32, 8)>>>(
        io, ioT_hi, (__half*)nullptr, LSEQ, DIM);

    // 8-9) bias-fold vectors
    compute_p<<<DIM / 128, 128>>>(W, bb, pv);
    compute_r<<<(BATCH * LSEQ) / 8, 256>>>(io, pv, rv);

    // 10) softmax(S + r) -> P fp16 (hi only)
    softmax_h<<<BATCH * LSEQ, 256>>>(s, rv, p_hi, LSEQ);

    // 11) out[b] = P[b] @ ioT[b]^T, 1-pass -> fp32 d_out
    {
        dim3 g(DIM / 128, LSEQ / 128, BATCH);
        gemm_split<1><<<g, 256, smem1>>>(p_hi, nullptr, ioT_hi, nullptr,
                                         out, nullptr, nullptr,
                                         LSEQ, DIM,
                                         (long long)LSEQ * LSEQ,
                                         (long long)DIM * LSEQ,
                                         (long long)LSEQ * DIM);
    }
}